// round 4
// baseline (speedup 1.0000x reference)
#include <cuda_runtime.h>
#include <cuda_bf16.h>
#include <math.h>

#define N_NODES 16384
#define E_EDGES 524288
#define F_IN    128
#define H_DIM   256
#define A_DIM   64

#define CAP      128     // bucket capacity per source node (max raw degree ~57)
#define LIST_CAP 160
#define NB       64      // nodes per fused block -> 2 CTAs/SM

// Scratch (static __device__ globals; zero-initialized at module load)
__device__ int   g_cnt[N_NODES];            // raw out-degree (re-zeroed by k_fused)
__device__ int   g_slot[N_NODES * CAP];     // bucketed dst lists (8 MB)
__device__ float g_gacc[H_DIM];             // zeroed by k_build each run

// ---------------------------------------------------------------------------
// Packed dual-FP32 helpers (Blackwell f32x2 -> SASS FFMA2). Bit-exact 2x fp32.
// ---------------------------------------------------------------------------
__device__ __forceinline__ unsigned long long ffma2(unsigned long long a,
                                                    unsigned long long b,
                                                    unsigned long long c) {
    unsigned long long d;
    asm("fma.rn.f32x2 %0, %1, %2, %3;" : "=l"(d) : "l"(a), "l"(b), "l"(c));
    return d;
}
__device__ __forceinline__ unsigned long long dup2(float x) {
    unsigned long long d;
    unsigned xb = __float_as_uint(x);
    asm("mov.b64 %0, {%1, %1};" : "=l"(d) : "r"(xb));
    return d;
}
__device__ __forceinline__ void unpack2(unsigned long long v, float& lo, float& hi) {
    unsigned a, b;
    asm("mov.b64 {%0, %1}, %2;" : "=r"(a), "=r"(b) : "l"(v));
    lo = __uint_as_float(a);
    hi = __uint_as_float(b);
}

// ---------------------------------------------------------------------------
// K1: single-pass bucket build. One edge per thread (max atomic MLP).
// Also zeroes g_gacc. g_cnt is zero on entry (invariant kept by k_fused).
// ---------------------------------------------------------------------------
__global__ void k_build(const int* __restrict__ ei) {
    int e = blockIdx.x * blockDim.x + threadIdx.x;
    if (e < H_DIM) g_gacc[e] = 0.0f;
    if (e < E_EDGES) {
        int s = ei[e];
        int d = ei[E_EDGES + e];
        int pos = atomicAdd(&g_cnt[s], 1);
        if (pos < CAP) g_slot[s * CAP + pos] = d;
    }
}

// ---------------------------------------------------------------------------
// K2: fused gather + GEMM + relu + node-sum.
// 256 threads, 64 nodes/block, grid = 256 -> occupancy 2 CTAs/SM so one
// block's L2-bound gather overlaps the co-resident block's FFMA2 GEMM.
// smem: ys[64*128] + ws[128*128] (bitmap/list aliased) + gpart[128] = 96.6KB
// ---------------------------------------------------------------------------
#define FUSED_SMEM_FLOATS (NB * 128 + 128 * 128 + 128)
#define FUSED_SMEM_BYTES  (FUSED_SMEM_FLOATS * 4)

__global__ __launch_bounds__(256, 2)
void k_fused(const float* __restrict__ X,
             const float* __restrict__ Wg,
             const float* __restrict__ bg) {
    extern __shared__ float smem[];
    float* ys    = smem;                 // [64][128]
    float* ws    = smem + NB * 128;      // [128 k][128 h] in phase B
    float* gpart = ws + 128 * 128;

    int tid  = threadIdx.x;              // 256
    int lane = tid & 31;
    int warp = tid >> 5;                 // 0..7
    int node0 = blockIdx.x * NB;

    // ---- Phase A: gather (bitmap + list alias into ws) ----
    unsigned* bitmap = ((unsigned*)ws) + warp * 512;
    int*      list   = ((int*)ws) + 8 * 512 + warp * LIST_CAP;
    const float4* X4 = (const float4*)X;

    for (int i = 0; i < NB / 8; i++) {
        int n_loc = warp * (NB / 8) + i;
        int n = node0 + n_loc;

        #pragma unroll
        for (int j = lane; j < 512; j += 32) bitmap[j] = 0u;
        __syncwarp();

        int len = g_cnt[n];
        if (len > CAP) len = CAP;
        const int* row = g_slot + n * CAP;
        int cnt = 0;
        for (int b = 0; b < len; b += 32) {
            int e = b + lane;
            int isnew = 0, d = 0;
            if (e < len) {
                d = row[e];
                unsigned m = 1u << (d & 31);
                unsigned old = atomicOr(&bitmap[d >> 5], m);
                isnew = ((old & m) == 0u);
            }
            unsigned bal = __ballot_sync(0xffffffffu, isnew);
            if (isnew) {
                int pos = cnt + __popc(bal & ((1u << lane) - 1u));
                if (pos < LIST_CAP) list[pos] = d;
            }
            cnt += __popc(bal);
        }
        if (cnt > LIST_CAP) cnt = LIST_CAP;
        __syncwarp();

        // acc = X[n] (identity) + sum_{unique d} X[d]; unroll 8 for MLP
        float4 acc = X4[(size_t)n * 32 + lane];
        int k = 0;
        for (; k + 8 <= cnt; k += 8) {
            int d0 = list[k + 0], d1 = list[k + 1], d2 = list[k + 2], d3 = list[k + 3];
            int d4 = list[k + 4], d5 = list[k + 5], d6 = list[k + 6], d7 = list[k + 7];
            float4 v0 = X4[(size_t)d0 * 32 + lane];
            float4 v1 = X4[(size_t)d1 * 32 + lane];
            float4 v2 = X4[(size_t)d2 * 32 + lane];
            float4 v3 = X4[(size_t)d3 * 32 + lane];
            float4 v4 = X4[(size_t)d4 * 32 + lane];
            float4 v5 = X4[(size_t)d5 * 32 + lane];
            float4 v6 = X4[(size_t)d6 * 32 + lane];
            float4 v7 = X4[(size_t)d7 * 32 + lane];
            acc.x += ((v0.x + v1.x) + (v2.x + v3.x)) + ((v4.x + v5.x) + (v6.x + v7.x));
            acc.y += ((v0.y + v1.y) + (v2.y + v3.y)) + ((v4.y + v5.y) + (v6.y + v7.y));
            acc.z += ((v0.z + v1.z) + (v2.z + v3.z)) + ((v4.z + v5.z) + (v6.z + v7.z));
            acc.w += ((v0.w + v1.w) + (v2.w + v3.w)) + ((v4.w + v5.w) + (v6.w + v7.w));
        }
        for (; k < cnt; k++) {
            float4 a = X4[(size_t)list[k] * 32 + lane];
            acc.x += a.x; acc.y += a.y; acc.z += a.z; acc.w += a.w;
        }
        float inv = 1.0f / (float)(1 + cnt);
        acc.x *= inv; acc.y *= inv; acc.z *= inv; acc.w *= inv;
        ((float4*)(ys + n_loc * 128))[lane] = acc;
    }

    __syncthreads();
    if (tid < NB) g_cnt[node0 + tid] = 0;   // restore invariant for next replay

    // ---- Phase B: packed-FFMA2 GEMM, 4n x 8h tiles ----
    int ng = tid >> 4;   // 0..15, 4 nodes each
    int hg = tid & 15;   // 0..15, 8 h each

    for (int hb = 0; hb < 2; hb++) {
        __syncthreads();  // ys ready / bitmap+list dead / prev ws+gpart consumed

        // W half -> k-major smem; h = idx&127 keeps STS conflict-free
        for (int idx = tid; idx < 128 * 32; idx += 256) {
            int h  = idx & 127;
            int k4 = idx >> 7;
            float4 w = ((const float4*)(Wg + (size_t)(hb * 128 + h) * F_IN))[k4];
            ws[(k4 * 4 + 0) * 128 + h] = w.x;
            ws[(k4 * 4 + 1) * 128 + h] = w.y;
            ws[(k4 * 4 + 2) * 128 + h] = w.z;
            ws[(k4 * 4 + 3) * 128 + h] = w.w;
        }
        if (tid < 128) gpart[tid] = 0.0f;
        __syncthreads();

        unsigned long long acc[4][4];
        #pragma unroll
        for (int i = 0; i < 4; i++)
            #pragma unroll
            for (int j = 0; j < 4; j++) acc[i][j] = 0ull;

        #pragma unroll 4
        for (int k4 = 0; k4 < 32; k4++) {
            float4 yv[4];
            #pragma unroll
            for (int i = 0; i < 4; i++)
                yv[i] = ((const float4*)(ys + (ng * 4 + i) * 128))[k4];
            #pragma unroll
            for (int kk = 0; kk < 4; kk++) {
                const float* wp = ws + (k4 * 4 + kk) * 128 + hg * 8;
                ulonglong2 wa = *((const ulonglong2*)wp);
                ulonglong2 wb = *((const ulonglong2*)(wp + 4));
                #pragma unroll
                for (int i = 0; i < 4; i++) {
                    float y = (kk == 0) ? yv[i].x : (kk == 1) ? yv[i].y
                             : (kk == 2) ? yv[i].z : yv[i].w;
                    unsigned long long yd = dup2(y);
                    acc[i][0] = ffma2(yd, wa.x, acc[i][0]);
                    acc[i][1] = ffma2(yd, wa.y, acc[i][1]);
                    acc[i][2] = ffma2(yd, wb.x, acc[i][2]);
                    acc[i][3] = ffma2(yd, wb.y, acc[i][3]);
                }
            }
        }

        // bias + relu per node, reduce over this thread's 4 nodes
        float bch[8];
        #pragma unroll
        for (int j = 0; j < 8; j++) bch[j] = bg[hb * 128 + hg * 8 + j];
        float hsum[8];
        #pragma unroll
        for (int j = 0; j < 8; j++) hsum[j] = 0.0f;
        #pragma unroll
        for (int i = 0; i < 4; i++) {
            #pragma unroll
            for (int j = 0; j < 4; j++) {
                float lo, hi;
                unpack2(acc[i][j], lo, hi);
                hsum[j * 2 + 0] += fmaxf(lo + bch[j * 2 + 0], 0.0f);
                hsum[j * 2 + 1] += fmaxf(hi + bch[j * 2 + 1], 0.0f);
            }
        }
        #pragma unroll
        for (int j = 0; j < 8; j++)
            atomicAdd(&gpart[hg * 8 + j], hsum[j]);
        __syncthreads();
        if (tid < 128) atomicAdd(&g_gacc[hb * 128 + tid], gpart[tid]);
    }
}

// ---------------------------------------------------------------------------
// K3: heads. out[0..63]=softmax(actor), out[64]=value
// ---------------------------------------------------------------------------
__global__ void k_head(const float* __restrict__ Wa1, const float* __restrict__ ba1,
                       const float* __restrict__ Wa2, const float* __restrict__ ba2,
                       const float* __restrict__ Wc1, const float* __restrict__ bc1,
                       const float* __restrict__ Wc2, const float* __restrict__ bc2,
                       float* __restrict__ out) {
    __shared__ float gg[H_DIM];
    __shared__ float hh[H_DIM];
    __shared__ float lg[A_DIM + 1];

    int t = threadIdx.x;             // 1024
    int lane = t & 31;
    int warp = t >> 5;               // 0..31

    if (t < H_DIM) gg[t] = g_gacc[t] * (1.0f / (float)N_NODES);
    __syncthreads();

    #pragma unroll
    for (int q = 0; q < 8; q++) {
        int o = warp * 8 + q;
        const float* Wrow = (o < 128) ? (Wa1 + (size_t)o * H_DIM)
                                      : (Wc1 + (size_t)(o - 128) * H_DIM);
        float bias = (o < 128) ? ba1[o] : bc1[o - 128];
        float s = 0.0f;
        #pragma unroll
        for (int j = 0; j < 8; j++)
            s += gg[lane + j * 32] * Wrow[lane + j * 32];
        #pragma unroll
        for (int off = 16; off > 0; off >>= 1)
            s += __shfl_down_sync(0xffffffffu, s, off);
        if (lane == 0) hh[o] = fmaxf(s + bias, 0.0f);
    }
    __syncthreads();

    #pragma unroll
    for (int q = 0; q < 2; q++) {
        int o = warp + q * 32;
        const float* Wrow = Wa2 + (size_t)o * (H_DIM / 2);
        float s = 0.0f;
        #pragma unroll
        for (int j = 0; j < 4; j++)
            s += hh[lane + j * 32] * Wrow[lane + j * 32];
        #pragma unroll
        for (int off = 16; off > 0; off >>= 1)
            s += __shfl_down_sync(0xffffffffu, s, off);
        if (lane == 0) lg[o] = s + ba2[o];
    }
    if (warp == 0) {
        float s = 0.0f;
        #pragma unroll
        for (int j = 0; j < 4; j++)
            s += hh[128 + lane + j * 32] * Wc2[lane + j * 32];
        #pragma unroll
        for (int off = 16; off > 0; off >>= 1)
            s += __shfl_down_sync(0xffffffffu, s, off);
        if (lane == 0) lg[A_DIM] = s + bc2[0];
    }
    __syncthreads();

    if (warp == 0) {
        float a = lg[lane], b = lg[lane + 32];
        float m = fmaxf(a, b);
        #pragma unroll
        for (int off = 16; off > 0; off >>= 1)
            m = fmaxf(m, __shfl_xor_sync(0xffffffffu, m, off));
        float ea = expf(a - m), eb = expf(b - m);
        float s = ea + eb;
        #pragma unroll
        for (int off = 16; off > 0; off >>= 1)
            s += __shfl_xor_sync(0xffffffffu, s, off);
        float inv = 1.0f / s;
        out[lane] = ea * inv;
        out[lane + 32] = eb * inv;
        if (lane == 0) out[A_DIM] = lg[A_DIM];
    }
}

// ---------------------------------------------------------------------------
extern "C" void kernel_launch(void* const* d_in, const int* in_sizes, int n_in,
                              void* d_out, int out_size) {
    const float* X   = (const float*)d_in[0];
    const int*   ei  = (const int*)  d_in[1];
    const float* Wg  = (const float*)d_in[2];
    const float* bg  = (const float*)d_in[3];
    const float* Wa1 = (const float*)d_in[4];
    const float* ba1 = (const float*)d_in[5];
    const float* Wa2 = (const float*)d_in[6];
    const float* ba2 = (const float*)d_in[7];
    const float* Wc1 = (const float*)d_in[8];
    const float* bc1 = (const float*)d_in[9];
    const float* Wc2 = (const float*)d_in[10];
    const float* bc2 = (const float*)d_in[11];
    float* out = (float*)d_out;

    cudaFuncSetAttribute(k_fused, cudaFuncAttributeMaxDynamicSharedMemorySize,
                         FUSED_SMEM_BYTES);

    k_build<<<E_EDGES / 256, 256>>>(ei);
    k_fused<<<N_NODES / NB, 256, FUSED_SMEM_BYTES>>>(X, Wg, bg);
    k_head<<<1, 1024>>>(Wa1, ba1, Wa2, ba2, Wc1, bc1, Wc2, bc2, out);
}

// round 5
// speedup vs baseline: 1.0162x; 1.0162x over previous
#include <cuda_runtime.h>
#include <cuda_fp16.h>
#include <math.h>

#define N_NODES 16384
#define E_EDGES 524288
#define F_IN    128
#define H_DIM   256
#define A_DIM   64

#define CAP      128     // bucket capacity per source node (max raw degree ~57)
#define LIST_CAP 160
#define NB       128     // nodes per fused block (round-3 config: best so far)

// Scratch (static __device__ globals; zero-initialized at module load)
__device__ int    g_cnt[N_NODES];            // raw out-degree (re-zeroed by k_fused)
__device__ int    g_slot[N_NODES * CAP];     // bucketed dst lists (8 MB)
__device__ float  g_gacc[H_DIM];             // zeroed by k_build each run
__device__ __half g_xh[N_NODES * F_IN];      // fp16 mirror of X (4 MB)

// ---------------------------------------------------------------------------
// Packed dual-FP32 helpers (Blackwell f32x2 -> SASS FFMA2). Bit-exact 2x fp32.
// ---------------------------------------------------------------------------
__device__ __forceinline__ unsigned long long ffma2(unsigned long long a,
                                                    unsigned long long b,
                                                    unsigned long long c) {
    unsigned long long d;
    asm("fma.rn.f32x2 %0, %1, %2, %3;" : "=l"(d) : "l"(a), "l"(b), "l"(c));
    return d;
}
__device__ __forceinline__ unsigned long long dup2(float x) {
    unsigned long long d;
    unsigned xb = __float_as_uint(x);
    asm("mov.b64 %0, {%1, %1};" : "=l"(d) : "r"(xb));
    return d;
}
__device__ __forceinline__ void unpack2(unsigned long long v, float& lo, float& hi) {
    unsigned a, b;
    asm("mov.b64 {%0, %1}, %2;" : "=r"(a), "=r"(b) : "l"(v));
    lo = __uint_as_float(a);
    hi = __uint_as_float(b);
}
__device__ __forceinline__ void hacc(float4& acc, uint2 v) {
    __half2 h0 = *reinterpret_cast<__half2*>(&v.x);
    __half2 h1 = *reinterpret_cast<__half2*>(&v.y);
    float2 f0 = __half22float2(h0);
    float2 f1 = __half22float2(h1);
    acc.x += f0.x; acc.y += f0.y; acc.z += f1.x; acc.w += f1.y;
}

// ---------------------------------------------------------------------------
// K1: single-pass bucket build + fp16 conversion of X + g_gacc zero.
// One edge per thread; each thread also converts 4 X elements to half.
// g_cnt is zero on entry (invariant restored by k_fused).
// ---------------------------------------------------------------------------
__global__ void k_build(const int* __restrict__ ei, const float* __restrict__ X) {
    int e = blockIdx.x * blockDim.x + threadIdx.x;   // 0 .. E_EDGES-1
    if (e < H_DIM) g_gacc[e] = 0.0f;
    // convert X -> half: E_EDGES threads x 4 elems = 2,097,152 = N*F  (exact)
    {
        float4 v = ((const float4*)X)[e];
        __half2 h0 = __floats2half2_rn(v.x, v.y);
        __half2 h1 = __floats2half2_rn(v.z, v.w);
        uint2 o;
        o.x = *reinterpret_cast<unsigned*>(&h0);
        o.y = *reinterpret_cast<unsigned*>(&h1);
        ((uint2*)g_xh)[e] = o;
    }
    int s = ei[e];
    int d = ei[E_EDGES + e];
    int pos = atomicAdd(&g_cnt[s], 1);
    if (pos < CAP) g_slot[s * CAP + pos] = d;
}

// ---------------------------------------------------------------------------
// K2: fused gather(fp16) + GEMM(fp32 FFMA2) + relu + node-sum.
// 256 threads, 128 nodes/block, grid = 128.
// Phase A: warp gathers 16 rows; smem-bitmap dedup; neighbor rows read from
//          g_xh (256 B/row, uint2/lane); identity row from fp32 X (exact).
// Phase B: ys[128x128] @ Wg^T with packed FFMA2, 8n x 8h register tiles.
// smem: ys[128*128] + ws[128*128] (bitmap/list aliased) + gpart[128]
// ---------------------------------------------------------------------------
#define FUSED_SMEM_FLOATS (NB * 128 + 128 * 128 + 128)
#define FUSED_SMEM_BYTES  (FUSED_SMEM_FLOATS * 4)

__global__ void k_fused(const float* __restrict__ X,
                        const float* __restrict__ Wg,
                        const float* __restrict__ bg) {
    extern __shared__ float smem[];
    float* ys    = smem;                 // [128][128]
    float* ws    = smem + NB * 128;      // [128 k][128 h] in phase B
    float* gpart = ws + 128 * 128;

    int tid  = threadIdx.x;              // 256
    int lane = tid & 31;
    int warp = tid >> 5;                 // 0..7
    int node0 = blockIdx.x * NB;

    // ---- Phase A: gather (bitmap + list alias into ws) ----
    unsigned* bitmap = ((unsigned*)ws) + warp * 512;
    int*      list   = ((int*)ws) + 8 * 512 + warp * LIST_CAP;
    const uint2* Xh2 = (const uint2*)g_xh;     // 32 uint2 per row

    for (int i = 0; i < NB / 8; i++) {
        int n_loc = warp * (NB / 8) + i;
        int n = node0 + n_loc;

        #pragma unroll
        for (int j = lane; j < 512; j += 32) bitmap[j] = 0u;
        __syncwarp();

        int len = g_cnt[n];
        if (len > CAP) len = CAP;
        const int* row = g_slot + n * CAP;
        int cnt = 0;
        for (int b = 0; b < len; b += 32) {
            int e = b + lane;
            int isnew = 0, d = 0;
            if (e < len) {
                d = row[e];
                unsigned m = 1u << (d & 31);
                unsigned old = atomicOr(&bitmap[d >> 5], m);
                isnew = ((old & m) == 0u);
            }
            unsigned bal = __ballot_sync(0xffffffffu, isnew);
            if (isnew) {
                int pos = cnt + __popc(bal & ((1u << lane) - 1u));
                if (pos < LIST_CAP) list[pos] = d;
            }
            cnt += __popc(bal);
        }
        if (cnt > LIST_CAP) cnt = LIST_CAP;
        __syncwarp();

        // acc = X[n] (exact fp32 identity) + sum_{unique d} Xh[d]
        float4 acc = ((const float4*)X)[(size_t)n * 32 + lane];
        int k = 0;
        for (; k + 8 <= cnt; k += 8) {
            uint2 v0 = Xh2[(size_t)list[k + 0] * 32 + lane];
            uint2 v1 = Xh2[(size_t)list[k + 1] * 32 + lane];
            uint2 v2 = Xh2[(size_t)list[k + 2] * 32 + lane];
            uint2 v3 = Xh2[(size_t)list[k + 3] * 32 + lane];
            uint2 v4 = Xh2[(size_t)list[k + 4] * 32 + lane];
            uint2 v5 = Xh2[(size_t)list[k + 5] * 32 + lane];
            uint2 v6 = Xh2[(size_t)list[k + 6] * 32 + lane];
            uint2 v7 = Xh2[(size_t)list[k + 7] * 32 + lane];
            hacc(acc, v0); hacc(acc, v1); hacc(acc, v2); hacc(acc, v3);
            hacc(acc, v4); hacc(acc, v5); hacc(acc, v6); hacc(acc, v7);
        }
        for (; k < cnt; k++)
            hacc(acc, Xh2[(size_t)list[k] * 32 + lane]);

        float inv = 1.0f / (float)(1 + cnt);
        acc.x *= inv; acc.y *= inv; acc.z *= inv; acc.w *= inv;
        ((float4*)(ys + n_loc * 128))[lane] = acc;
    }

    __syncthreads();
    if (tid < NB) g_cnt[node0 + tid] = 0;   // restore invariant for next replay

    // ---- Phase B: packed-FFMA2 GEMM, 8n x 8h tiles ----
    int ng = tid >> 4;   // 0..15, 8 nodes each
    int hg = tid & 15;   // 0..15, 8 h each

    for (int hb = 0; hb < 2; hb++) {
        __syncthreads();  // ys ready / bitmap+list dead / prev ws+gpart consumed

        // W half -> k-major smem; h = idx&127 keeps STS conflict-free
        for (int idx = tid; idx < 128 * 32; idx += 256) {
            int h  = idx & 127;
            int k4 = idx >> 7;
            float4 w = ((const float4*)(Wg + (size_t)(hb * 128 + h) * F_IN))[k4];
            ws[(k4 * 4 + 0) * 128 + h] = w.x;
            ws[(k4 * 4 + 1) * 128 + h] = w.y;
            ws[(k4 * 4 + 2) * 128 + h] = w.z;
            ws[(k4 * 4 + 3) * 128 + h] = w.w;
        }
        if (tid < 128) gpart[tid] = 0.0f;
        __syncthreads();

        unsigned long long acc[8][4];
        #pragma unroll
        for (int i = 0; i < 8; i++)
            #pragma unroll
            for (int j = 0; j < 4; j++) acc[i][j] = 0ull;

        #pragma unroll 2
        for (int k4 = 0; k4 < 32; k4++) {
            float4 yv[8];
            #pragma unroll
            for (int i = 0; i < 8; i++)
                yv[i] = ((const float4*)(ys + (ng * 8 + i) * 128))[k4];
            #pragma unroll
            for (int kk = 0; kk < 4; kk++) {
                const float* wp = ws + (k4 * 4 + kk) * 128 + hg * 8;
                ulonglong2 wa = *((const ulonglong2*)wp);
                ulonglong2 wb = *((const ulonglong2*)(wp + 4));
                #pragma unroll
                for (int i = 0; i < 8; i++) {
                    float y = (kk == 0) ? yv[i].x : (kk == 1) ? yv[i].y
                             : (kk == 2) ? yv[i].z : yv[i].w;
                    unsigned long long yd = dup2(y);
                    acc[i][0] = ffma2(yd, wa.x, acc[i][0]);
                    acc[i][1] = ffma2(yd, wa.y, acc[i][1]);
                    acc[i][2] = ffma2(yd, wb.x, acc[i][2]);
                    acc[i][3] = ffma2(yd, wb.y, acc[i][3]);
                }
            }
        }

        // bias + relu per node, reduce over this thread's 8 nodes
        float bch[8];
        #pragma unroll
        for (int j = 0; j < 8; j++) bch[j] = bg[hb * 128 + hg * 8 + j];
        float hsum[8];
        #pragma unroll
        for (int j = 0; j < 8; j++) hsum[j] = 0.0f;
        #pragma unroll
        for (int i = 0; i < 8; i++) {
            #pragma unroll
            for (int j = 0; j < 4; j++) {
                float lo, hi;
                unpack2(acc[i][j], lo, hi);
                hsum[j * 2 + 0] += fmaxf(lo + bch[j * 2 + 0], 0.0f);
                hsum[j * 2 + 1] += fmaxf(hi + bch[j * 2 + 1], 0.0f);
            }
        }
        #pragma unroll
        for (int j = 0; j < 8; j++)
            atomicAdd(&gpart[hg * 8 + j], hsum[j]);
        __syncthreads();
        if (tid < 128) atomicAdd(&g_gacc[hb * 128 + tid], gpart[tid]);
    }
}

// ---------------------------------------------------------------------------
// K3: heads. out[0..63]=softmax(actor), out[64]=value
// ---------------------------------------------------------------------------
__global__ void k_head(const float* __restrict__ Wa1, const float* __restrict__ ba1,
                       const float* __restrict__ Wa2, const float* __restrict__ ba2,
                       const float* __restrict__ Wc1, const float* __restrict__ bc1,
                       const float* __restrict__ Wc2, const float* __restrict__ bc2,
                       float* __restrict__ out) {
    __shared__ float gg[H_DIM];
    __shared__ float hh[H_DIM];
    __shared__ float lg[A_DIM + 1];

    int t = threadIdx.x;             // 1024
    int lane = t & 31;
    int warp = t >> 5;               // 0..31

    if (t < H_DIM) gg[t] = g_gacc[t] * (1.0f / (float)N_NODES);
    __syncthreads();

    #pragma unroll
    for (int q = 0; q < 8; q++) {
        int o = warp * 8 + q;
        const float* Wrow = (o < 128) ? (Wa1 + (size_t)o * H_DIM)
                                      : (Wc1 + (size_t)(o - 128) * H_DIM);
        float bias = (o < 128) ? ba1[o] : bc1[o - 128];
        float s = 0.0f;
        #pragma unroll
        for (int j = 0; j < 8; j++)
            s += gg[lane + j * 32] * Wrow[lane + j * 32];
        #pragma unroll
        for (int off = 16; off > 0; off >>= 1)
            s += __shfl_down_sync(0xffffffffu, s, off);
        if (lane == 0) hh[o] = fmaxf(s + bias, 0.0f);
    }
    __syncthreads();

    #pragma unroll
    for (int q = 0; q < 2; q++) {
        int o = warp + q * 32;
        const float* Wrow = Wa2 + (size_t)o * (H_DIM / 2);
        float s = 0.0f;
        #pragma unroll
        for (int j = 0; j < 4; j++)
            s += hh[lane + j * 32] * Wrow[lane + j * 32];
        #pragma unroll
        for (int off = 16; off > 0; off >>= 1)
            s += __shfl_down_sync(0xffffffffu, s, off);
        if (lane == 0) lg[o] = s + ba2[o];
    }
    if (warp == 0) {
        float s = 0.0f;
        #pragma unroll
        for (int j = 0; j < 4; j++)
            s += hh[128 + lane + j * 32] * Wc2[lane + j * 32];
        #pragma unroll
        for (int off = 16; off > 0; off >>= 1)
            s += __shfl_down_sync(0xffffffffu, s, off);
        if (lane == 0) lg[A_DIM] = s + bc2[0];
    }
    __syncthreads();

    if (warp == 0) {
        float a = lg[lane], b = lg[lane + 32];
        float m = fmaxf(a, b);
        #pragma unroll
        for (int off = 16; off > 0; off >>= 1)
            m = fmaxf(m, __shfl_xor_sync(0xffffffffu, m, off));
        float ea = expf(a - m), eb = expf(b - m);
        float s = ea + eb;
        #pragma unroll
        for (int off = 16; off > 0; off >>= 1)
            s += __shfl_xor_sync(0xffffffffu, s, off);
        float inv = 1.0f / s;
        out[lane] = ea * inv;
        out[lane + 32] = eb * inv;
        if (lane == 0) out[A_DIM] = lg[A_DIM];
    }
}

// ---------------------------------------------------------------------------
extern "C" void kernel_launch(void* const* d_in, const int* in_sizes, int n_in,
                              void* d_out, int out_size) {
    const float* X   = (const float*)d_in[0];
    const int*   ei  = (const int*)  d_in[1];
    const float* Wg  = (const float*)d_in[2];
    const float* bg  = (const float*)d_in[3];
    const float* Wa1 = (const float*)d_in[4];
    const float* ba1 = (const float*)d_in[5];
    const float* Wa2 = (const float*)d_in[6];
    const float* ba2 = (const float*)d_in[7];
    const float* Wc1 = (const float*)d_in[8];
    const float* bc1 = (const float*)d_in[9];
    const float* Wc2 = (const float*)d_in[10];
    const float* bc2 = (const float*)d_in[11];
    float* out = (float*)d_out;

    cudaFuncSetAttribute(k_fused, cudaFuncAttributeMaxDynamicSharedMemorySize,
                         FUSED_SMEM_BYTES);

    k_build<<<E_EDGES / 256, 256>>>(ei, X);
    k_fused<<<N_NODES / NB, 256, FUSED_SMEM_BYTES>>>(X, Wg, bg);
    k_head<<<1, 1024>>>(Wa1, ba1, Wa2, ba2, Wc1, bc1, Wc2, bc2, out);
}

// round 6
// speedup vs baseline: 1.0452x; 1.0286x over previous
#include <cuda_runtime.h>
#include <cuda_fp16.h>
#include <math.h>

#define N_NODES 16384
#define E_EDGES 524288
#define F_IN    128
#define H_DIM   256
#define A_DIM   64

#define CAP      128     // bucket capacity per source node (max raw degree ~57)
#define LIST_CAP 160
#define NB       128     // nodes per fused block, grid = 128

// Scratch (static __device__ globals; zero-initialized at module load)
__device__ int   g_cnt[N_NODES];            // raw out-degree (re-zeroed by k_fused)
__device__ int   g_slot[N_NODES * CAP];     // bucketed dst lists (8 MB)
__device__ float g_gacc[H_DIM];             // zeroed by k_build each run

// ---------------------------------------------------------------------------
// Packed dual-FP32 helpers (Blackwell f32x2 -> SASS FFMA2). Bit-exact 2x fp32.
// ---------------------------------------------------------------------------
__device__ __forceinline__ unsigned long long ffma2(unsigned long long a,
                                                    unsigned long long b,
                                                    unsigned long long c) {
    unsigned long long d;
    asm("fma.rn.f32x2 %0, %1, %2, %3;" : "=l"(d) : "l"(a), "l"(b), "l"(c));
    return d;
}
__device__ __forceinline__ unsigned long long dup2(float x) {
    unsigned long long d;
    unsigned xb = __float_as_uint(x);
    asm("mov.b64 %0, {%1, %1};" : "=l"(d) : "r"(xb));
    return d;
}
__device__ __forceinline__ unsigned long long pack2(float lo, float hi) {
    unsigned long long d;
    asm("mov.b64 %0, {%1, %2};" : "=l"(d)
        : "r"(__float_as_uint(lo)), "r"(__float_as_uint(hi)));
    return d;
}
__device__ __forceinline__ void unpack2(unsigned long long v, float& lo, float& hi) {
    unsigned a, b;
    asm("mov.b64 {%0, %1}, %2;" : "=r"(a), "=r"(b) : "l"(v));
    lo = __uint_as_float(a);
    hi = __uint_as_float(b);
}

// ---------------------------------------------------------------------------
// K1: single-pass bucket build. One edge per thread. Zeroes g_gacc.
// g_cnt is zero on entry (invariant restored by k_fused).
// ---------------------------------------------------------------------------
__global__ void k_build(const int* __restrict__ ei) {
    int e = blockIdx.x * blockDim.x + threadIdx.x;
    if (e < H_DIM) g_gacc[e] = 0.0f;
    if (e < E_EDGES) {
        int s = ei[e];
        int d = ei[E_EDGES + e];
        int pos = atomicAdd(&g_cnt[s], 1);
        if (pos < CAP) g_slot[s * CAP + pos] = d;
    }
}

// ---------------------------------------------------------------------------
// K2: fused gather + GEMM + relu + node-sum.
// 256 threads, 128 nodes/block, grid = 128.
// Phase A: warp gathers 16 rows (smem bitmap dedup, fp32 float4 loads).
// Phase B: warp w owns nodes w*16..w*16+15; lane l owns h = l*4..l*4+3 of
//          the current 128-h half. W loads ws+k*128+l*4 are CONFLICT-FREE
//          (32 lanes span exactly one 512B row); y reads are warp-uniform
//          broadcasts. Packed FFMA2 accumulators acc[16][2].
// smem: ys[128*128] + ws[128*128] (bitmap/list aliased) + gpart[128]
// ---------------------------------------------------------------------------
#define FUSED_SMEM_FLOATS (NB * 128 + 128 * 128 + 128)
#define FUSED_SMEM_BYTES  (FUSED_SMEM_FLOATS * 4)

__global__ void k_fused(const float* __restrict__ X,
                        const float* __restrict__ Wg,
                        const float* __restrict__ bg) {
    extern __shared__ float smem[];
    float* ys    = smem;                 // [128 nodes][128 k]
    float* ws    = smem + NB * 128;      // [128 k][128 h] in phase B
    float* gpart = ws + 128 * 128;

    int tid  = threadIdx.x;              // 256
    int lane = tid & 31;
    int warp = tid >> 5;                 // 0..7
    int node0 = blockIdx.x * NB;

    // ---- Phase A: gather (bitmap + list alias into ws) ----
    unsigned* bitmap = ((unsigned*)ws) + warp * 512;
    int*      list   = ((int*)ws) + 8 * 512 + warp * LIST_CAP;
    const float4* X4 = (const float4*)X;

    for (int i = 0; i < 16; i++) {
        int n_loc = warp * 16 + i;
        int n = node0 + n_loc;

        #pragma unroll
        for (int j = lane; j < 512; j += 32) bitmap[j] = 0u;
        __syncwarp();

        int len = g_cnt[n];
        if (len > CAP) len = CAP;
        const int* row = g_slot + n * CAP;
        int cnt = 0;
        for (int b = 0; b < len; b += 32) {
            int e = b + lane;
            int isnew = 0, d = 0;
            if (e < len) {
                d = row[e];
                unsigned m = 1u << (d & 31);
                unsigned old = atomicOr(&bitmap[d >> 5], m);
                isnew = ((old & m) == 0u);
            }
            unsigned bal = __ballot_sync(0xffffffffu, isnew);
            if (isnew) {
                int pos = cnt + __popc(bal & ((1u << lane) - 1u));
                if (pos < LIST_CAP) list[pos] = d;
            }
            cnt += __popc(bal);
        }
        if (cnt > LIST_CAP) cnt = LIST_CAP;
        __syncwarp();

        // acc = X[n] (identity) + sum_{unique d} X[d]; unroll 8 for MLP
        float4 acc = X4[(size_t)n * 32 + lane];
        int k = 0;
        for (; k + 8 <= cnt; k += 8) {
            int d0 = list[k + 0], d1 = list[k + 1], d2 = list[k + 2], d3 = list[k + 3];
            int d4 = list[k + 4], d5 = list[k + 5], d6 = list[k + 6], d7 = list[k + 7];
            float4 v0 = X4[(size_t)d0 * 32 + lane];
            float4 v1 = X4[(size_t)d1 * 32 + lane];
            float4 v2 = X4[(size_t)d2 * 32 + lane];
            float4 v3 = X4[(size_t)d3 * 32 + lane];
            float4 v4 = X4[(size_t)d4 * 32 + lane];
            float4 v5 = X4[(size_t)d5 * 32 + lane];
            float4 v6 = X4[(size_t)d6 * 32 + lane];
            float4 v7 = X4[(size_t)d7 * 32 + lane];
            acc.x += ((v0.x + v1.x) + (v2.x + v3.x)) + ((v4.x + v5.x) + (v6.x + v7.x));
            acc.y += ((v0.y + v1.y) + (v2.y + v3.y)) + ((v4.y + v5.y) + (v6.y + v7.y));
            acc.z += ((v0.z + v1.z) + (v2.z + v3.z)) + ((v4.z + v5.z) + (v6.z + v7.z));
            acc.w += ((v0.w + v1.w) + (v2.w + v3.w)) + ((v4.w + v5.w) + (v6.w + v7.w));
        }
        for (; k < cnt; k++) {
            float4 a = X4[(size_t)list[k] * 32 + lane];
            acc.x += a.x; acc.y += a.y; acc.z += a.z; acc.w += a.w;
        }
        float inv = 1.0f / (float)(1 + cnt);
        acc.x *= inv; acc.y *= inv; acc.z *= inv; acc.w *= inv;
        ((float4*)(ys + n_loc * 128))[lane] = acc;
    }

    __syncthreads();
    if (tid < NB) g_cnt[node0 + tid] = 0;   // restore invariant for next replay

    // ---- Phase B: conflict-free packed-FFMA2 GEMM ----
    // warp -> nodes [warp*16, warp*16+16); lane -> h = lane*4 .. lane*4+3
    int nbase = warp * 16;

    for (int hb = 0; hb < 2; hb++) {
        __syncthreads();  // ys ready / bitmap+list dead / prev ws+gpart consumed

        // W half -> k-major smem (consecutive tid -> consecutive h: STS clean)
        for (int idx = tid; idx < 128 * 32; idx += 256) {
            int h  = idx & 127;
            int k4 = idx >> 7;
            float4 w = ((const float4*)(Wg + (size_t)(hb * 128 + h) * F_IN))[k4];
            ws[(k4 * 4 + 0) * 128 + h] = w.x;
            ws[(k4 * 4 + 1) * 128 + h] = w.y;
            ws[(k4 * 4 + 2) * 128 + h] = w.z;
            ws[(k4 * 4 + 3) * 128 + h] = w.w;
        }
        if (tid < 128) gpart[tid] = 0.0f;
        __syncthreads();

        unsigned long long acc[16][2];
        #pragma unroll
        for (int n = 0; n < 16; n++) { acc[n][0] = 0ull; acc[n][1] = 0ull; }

        #pragma unroll 2
        for (int k4 = 0; k4 < 32; k4++) {
            #pragma unroll
            for (int kk = 0; kk < 4; kk++) {
                int k = k4 * 4 + kk;
                // conflict-free: lanes 0..31 cover one full 512B k-row
                float4 wv = *((const float4*)(ws + k * 128 + lane * 4));
                unsigned long long wlo = pack2(wv.x, wv.y);
                unsigned long long whi = pack2(wv.z, wv.w);
                #pragma unroll
                for (int n = 0; n < 16; n++) {
                    // warp-uniform address -> broadcast LDS (N=1, free)
                    unsigned long long yd = dup2(ys[(nbase + n) * 128 + k]);
                    acc[n][0] = ffma2(yd, wlo, acc[n][0]);
                    acc[n][1] = ffma2(yd, whi, acc[n][1]);
                }
            }
        }

        // bias + relu per node, reduce over this warp's 16 nodes
        float b0 = bg[hb * 128 + lane * 4 + 0];
        float b1 = bg[hb * 128 + lane * 4 + 1];
        float b2 = bg[hb * 128 + lane * 4 + 2];
        float b3 = bg[hb * 128 + lane * 4 + 3];
        float h0 = 0.f, h1 = 0.f, h2 = 0.f, h3 = 0.f;
        #pragma unroll
        for (int n = 0; n < 16; n++) {
            float lo, hi;
            unpack2(acc[n][0], lo, hi);
            h0 += fmaxf(lo + b0, 0.0f);
            h1 += fmaxf(hi + b1, 0.0f);
            unpack2(acc[n][1], lo, hi);
            h2 += fmaxf(lo + b2, 0.0f);
            h3 += fmaxf(hi + b3, 0.0f);
        }
        atomicAdd(&gpart[lane * 4 + 0], h0);
        atomicAdd(&gpart[lane * 4 + 1], h1);
        atomicAdd(&gpart[lane * 4 + 2], h2);
        atomicAdd(&gpart[lane * 4 + 3], h3);
        __syncthreads();
        if (tid < 128) atomicAdd(&g_gacc[hb * 128 + tid], gpart[tid]);
    }
}

// ---------------------------------------------------------------------------
// K3: heads. out[0..63]=softmax(actor), out[64]=value
// ---------------------------------------------------------------------------
__global__ void k_head(const float* __restrict__ Wa1, const float* __restrict__ ba1,
                       const float* __restrict__ Wa2, const float* __restrict__ ba2,
                       const float* __restrict__ Wc1, const float* __restrict__ bc1,
                       const float* __restrict__ Wc2, const float* __restrict__ bc2,
                       float* __restrict__ out) {
    __shared__ float gg[H_DIM];
    __shared__ float hh[H_DIM];
    __shared__ float lg[A_DIM + 1];

    int t = threadIdx.x;             // 1024
    int lane = t & 31;
    int warp = t >> 5;               // 0..31

    if (t < H_DIM) gg[t] = g_gacc[t] * (1.0f / (float)N_NODES);
    __syncthreads();

    #pragma unroll
    for (int q = 0; q < 8; q++) {
        int o = warp * 8 + q;
        const float* Wrow = (o < 128) ? (Wa1 + (size_t)o * H_DIM)
                                      : (Wc1 + (size_t)(o - 128) * H_DIM);
        float bias = (o < 128) ? ba1[o] : bc1[o - 128];
        float s = 0.0f;
        #pragma unroll
        for (int j = 0; j < 8; j++)
            s += gg[lane + j * 32] * Wrow[lane + j * 32];
        #pragma unroll
        for (int off = 16; off > 0; off >>= 1)
            s += __shfl_down_sync(0xffffffffu, s, off);
        if (lane == 0) hh[o] = fmaxf(s + bias, 0.0f);
    }
    __syncthreads();

    #pragma unroll
    for (int q = 0; q < 2; q++) {
        int o = warp + q * 32;
        const float* Wrow = Wa2 + (size_t)o * (H_DIM / 2);
        float s = 0.0f;
        #pragma unroll
        for (int j = 0; j < 4; j++)
            s += hh[lane + j * 32] * Wrow[lane + j * 32];
        #pragma unroll
        for (int off = 16; off > 0; off >>= 1)
            s += __shfl_down_sync(0xffffffffu, s, off);
        if (lane == 0) lg[o] = s + ba2[o];
    }
    if (warp == 0) {
        float s = 0.0f;
        #pragma unroll
        for (int j = 0; j < 4; j++)
            s += hh[128 + lane + j * 32] * Wc2[lane + j * 32];
        #pragma unroll
        for (int off = 16; off > 0; off >>= 1)
            s += __shfl_down_sync(0xffffffffu, s, off);
        if (lane == 0) lg[A_DIM] = s + bc2[0];
    }
    __syncthreads();

    if (warp == 0) {
        float a = lg[lane], b = lg[lane + 32];
        float m = fmaxf(a, b);
        #pragma unroll
        for (int off = 16; off > 0; off >>= 1)
            m = fmaxf(m, __shfl_xor_sync(0xffffffffu, m, off));
        float ea = expf(a - m), eb = expf(b - m);
        float s = ea + eb;
        #pragma unroll
        for (int off = 16; off > 0; off >>= 1)
            s += __shfl_xor_sync(0xffffffffu, s, off);
        float inv = 1.0f / s;
        out[lane] = ea * inv;
        out[lane + 32] = eb * inv;
        if (lane == 0) out[A_DIM] = lg[A_DIM];
    }
}

// ---------------------------------------------------------------------------
extern "C" void kernel_launch(void* const* d_in, const int* in_sizes, int n_in,
                              void* d_out, int out_size) {
    const float* X   = (const float*)d_in[0];
    const int*   ei  = (const int*)  d_in[1];
    const float* Wg  = (const float*)d_in[2];
    const float* bg  = (const float*)d_in[3];
    const float* Wa1 = (const float*)d_in[4];
    const float* ba1 = (const float*)d_in[5];
    const float* Wa2 = (const float*)d_in[6];
    const float* ba2 = (const float*)d_in[7];
    const float* Wc1 = (const float*)d_in[8];
    const float* bc1 = (const float*)d_in[9];
    const float* Wc2 = (const float*)d_in[10];
    const float* bc2 = (const float*)d_in[11];
    float* out = (float*)d_out;

    cudaFuncSetAttribute(k_fused, cudaFuncAttributeMaxDynamicSharedMemorySize,
                         FUSED_SMEM_BYTES);

    k_build<<<E_EDGES / 256, 256>>>(ei);
    k_fused<<<N_NODES / NB, 256, FUSED_SMEM_BYTES>>>(X, Wg, bg);
    k_head<<<1, 1024>>>(Wa1, ba1, Wa2, ba2, Wc1, bc1, Wc2, bc2, out);
}

// round 7
// speedup vs baseline: 1.3060x; 1.2495x over previous
#include <cuda_runtime.h>
#include <cuda_fp16.h>
#include <math.h>

#define N_NODES 16384
#define E_EDGES 524288
#define F_IN    128
#define H_DIM   256
#define A_DIM   64

#define CAP      128     // bucket capacity per source node (max raw degree ~57)
#define LIST_CAP 160
#define GW       16      // warps (nodes) per gather block
#define NB       128     // nodes per gemm block

// Scratch (static __device__ globals; zero-initialized at module load)
__device__ int   g_cnt[N_NODES];            // raw out-degree (re-zeroed by k_gather)
__device__ int   g_slot[N_NODES * CAP];     // bucketed dst lists (8 MB)
__device__ float g_y[N_NODES * F_IN];       // normalized aggregated features (8 MB)
__device__ float g_gacc[H_DIM];             // zeroed by k_build each run

// ---------------------------------------------------------------------------
// Packed dual-FP32 helpers (Blackwell f32x2 -> SASS FFMA2). Bit-exact 2x fp32.
// ---------------------------------------------------------------------------
__device__ __forceinline__ unsigned long long ffma2(unsigned long long a,
                                                    unsigned long long b,
                                                    unsigned long long c) {
    unsigned long long d;
    asm("fma.rn.f32x2 %0, %1, %2, %3;" : "=l"(d) : "l"(a), "l"(b), "l"(c));
    return d;
}
__device__ __forceinline__ unsigned long long dup2(float x) {
    unsigned long long d;
    unsigned xb = __float_as_uint(x);
    asm("mov.b64 %0, {%1, %1};" : "=l"(d) : "r"(xb));
    return d;
}
__device__ __forceinline__ unsigned long long pack2(float lo, float hi) {
    unsigned long long d;
    asm("mov.b64 %0, {%1, %2};" : "=l"(d)
        : "r"(__float_as_uint(lo)), "r"(__float_as_uint(hi)));
    return d;
}
__device__ __forceinline__ void unpack2(unsigned long long v, float& lo, float& hi) {
    unsigned a, b;
    asm("mov.b64 {%0, %1}, %2;" : "=r"(a), "=r"(b) : "l"(v));
    lo = __uint_as_float(a);
    hi = __uint_as_float(b);
}

// ---------------------------------------------------------------------------
// K1: single-pass bucket build. One edge per thread. Zeroes g_gacc.
// g_cnt is zero on entry (invariant restored by k_gather).
// ---------------------------------------------------------------------------
__global__ void k_build(const int* __restrict__ ei) {
    int e = blockIdx.x * blockDim.x + threadIdx.x;
    if (e < H_DIM) g_gacc[e] = 0.0f;
    if (e < E_EDGES) {
        int s = ei[e];
        int d = ei[E_EDGES + e];
        int pos = atomicAdd(&g_cnt[s], 1);
        if (pos < CAP) g_slot[s * CAP + pos] = d;
    }
}

// ---------------------------------------------------------------------------
// K2: gather. ONE WARP PER NODE, 16 warps/block, 42KB static smem ->
// 4 blocks/SM = 64 warps/SM hiding L2 latency (the round-6 fused kernel
// only had 8). Dedup via per-warp smem bitmap, then unroll-8 row loads.
// Writes Y[n] = (X[n] + sum_unique X[d]) / (1+cnt) to global.
// ---------------------------------------------------------------------------
__global__ __launch_bounds__(GW * 32, 4)
void k_gather(const float* __restrict__ X) {
    __shared__ unsigned bitmap_s[GW * 512];   // 32 KB
    __shared__ int      list_s[GW * LIST_CAP];// 10 KB

    int lane = threadIdx.x & 31;
    int warp = threadIdx.x >> 5;              // 0..15
    int n = blockIdx.x * GW + warp;           // node (grid covers all 16384)

    unsigned* bitmap = bitmap_s + warp * 512;
    int*      list   = list_s + warp * LIST_CAP;
    const float4* X4 = (const float4*)X;

    #pragma unroll
    for (int j = lane; j < 512; j += 32) bitmap[j] = 0u;
    __syncwarp();

    int len = g_cnt[n];
    if (len > CAP) len = CAP;
    const int* row = g_slot + n * CAP;
    int cnt = 0;
    for (int b = 0; b < len; b += 32) {
        int e = b + lane;
        int isnew = 0, d = 0;
        if (e < len) {
            d = row[e];
            unsigned m = 1u << (d & 31);
            unsigned old = atomicOr(&bitmap[d >> 5], m);
            isnew = ((old & m) == 0u);
        }
        unsigned bal = __ballot_sync(0xffffffffu, isnew);
        if (isnew) {
            int pos = cnt + __popc(bal & ((1u << lane) - 1u));
            if (pos < LIST_CAP) list[pos] = d;
        }
        cnt += __popc(bal);
    }
    if (cnt > LIST_CAP) cnt = LIST_CAP;
    __syncwarp();

    // acc = X[n] (identity) + sum_{unique d} X[d]; unroll 8 for MLP
    float4 acc = X4[(size_t)n * 32 + lane];
    int k = 0;
    for (; k + 8 <= cnt; k += 8) {
        int d0 = list[k + 0], d1 = list[k + 1], d2 = list[k + 2], d3 = list[k + 3];
        int d4 = list[k + 4], d5 = list[k + 5], d6 = list[k + 6], d7 = list[k + 7];
        float4 v0 = X4[(size_t)d0 * 32 + lane];
        float4 v1 = X4[(size_t)d1 * 32 + lane];
        float4 v2 = X4[(size_t)d2 * 32 + lane];
        float4 v3 = X4[(size_t)d3 * 32 + lane];
        float4 v4 = X4[(size_t)d4 * 32 + lane];
        float4 v5 = X4[(size_t)d5 * 32 + lane];
        float4 v6 = X4[(size_t)d6 * 32 + lane];
        float4 v7 = X4[(size_t)d7 * 32 + lane];
        acc.x += ((v0.x + v1.x) + (v2.x + v3.x)) + ((v4.x + v5.x) + (v6.x + v7.x));
        acc.y += ((v0.y + v1.y) + (v2.y + v3.y)) + ((v4.y + v5.y) + (v6.y + v7.y));
        acc.z += ((v0.z + v1.z) + (v2.z + v3.z)) + ((v4.z + v5.z) + (v6.z + v7.z));
        acc.w += ((v0.w + v1.w) + (v2.w + v3.w)) + ((v4.w + v5.w) + (v6.w + v7.w));
    }
    for (; k < cnt; k++) {
        float4 a = X4[(size_t)list[k] * 32 + lane];
        acc.x += a.x; acc.y += a.y; acc.z += a.z; acc.w += a.w;
    }
    float inv = 1.0f / (float)(1 + cnt);
    acc.x *= inv; acc.y *= inv; acc.z *= inv; acc.w *= inv;
    ((float4*)(g_y + (size_t)n * F_IN))[lane] = acc;

    if (lane == 0) g_cnt[n] = 0;   // restore invariant for next replay
}

// ---------------------------------------------------------------------------
// K3: GEMM + relu + node-sum.  512 threads, 128 nodes/block, grid = 128.
// Warp w owns nodes w*8..w*8+7; lane l owns h = l*4..l*4+3 of the current
// 128-h half. Conflict-free W LDS (lanes span one 512B k-row); y reads are
// warp-uniform float4 broadcasts. Packed FFMA2 accumulators acc[8][2].
// smem: ys[128*128] + ws[128*128] + gpart[128] = 128.5 KB dynamic
// ---------------------------------------------------------------------------
#define GEMM_SMEM_FLOATS (NB * 128 + 128 * 128 + 128)
#define GEMM_SMEM_BYTES  (GEMM_SMEM_FLOATS * 4)

__global__ void k_gemm(const float* __restrict__ Wg, const float* __restrict__ bg) {
    extern __shared__ float smem[];
    float* ys    = smem;                 // [128 nodes][128 k]
    float* ws    = smem + NB * 128;      // [128 k][128 h]
    float* gpart = ws + 128 * 128;

    int tid  = threadIdx.x;              // 512
    int lane = tid & 31;
    int warp = tid >> 5;                 // 0..15
    int node0 = blockIdx.x * NB;

    // Load Y tile (coalesced: consecutive tid -> consecutive k4)
    const float4* Y4 = (const float4*)g_y;
    for (int idx = tid; idx < NB * 32; idx += 512) {
        int r  = idx >> 5;
        int k4 = idx & 31;
        ((float4*)(ys + r * 128))[k4] = Y4[(size_t)(node0 + r) * 32 + k4];
    }

    int nbase = warp * 8;

    for (int hb = 0; hb < 2; hb++) {
        __syncthreads();  // ys ready / prev ws+gpart consumed

        // W half -> k-major smem (consecutive tid -> consecutive h: STS clean)
        for (int idx = tid; idx < 128 * 32; idx += 512) {
            int h  = idx & 127;
            int k4 = idx >> 7;
            float4 w = ((const float4*)(Wg + (size_t)(hb * 128 + h) * F_IN))[k4];
            ws[(k4 * 4 + 0) * 128 + h] = w.x;
            ws[(k4 * 4 + 1) * 128 + h] = w.y;
            ws[(k4 * 4 + 2) * 128 + h] = w.z;
            ws[(k4 * 4 + 3) * 128 + h] = w.w;
        }
        if (tid < 128) gpart[tid] = 0.0f;
        __syncthreads();

        unsigned long long acc[8][2];
        #pragma unroll
        for (int n = 0; n < 8; n++) { acc[n][0] = 0ull; acc[n][1] = 0ull; }

        #pragma unroll 2
        for (int k4 = 0; k4 < 32; k4++) {
            // y: warp-uniform float4 broadcasts (1 LDS.128 per node per k4)
            float4 yv[8];
            #pragma unroll
            for (int n = 0; n < 8; n++)
                yv[n] = *((const float4*)(ys + (nbase + n) * 128 + k4 * 4));
            #pragma unroll
            for (int kk = 0; kk < 4; kk++) {
                int k = k4 * 4 + kk;
                // conflict-free: lanes 0..31 cover one full 512B k-row
                float4 wv = *((const float4*)(ws + k * 128 + lane * 4));
                unsigned long long wlo = pack2(wv.x, wv.y);
                unsigned long long whi = pack2(wv.z, wv.w);
                #pragma unroll
                for (int n = 0; n < 8; n++) {
                    float y = (kk == 0) ? yv[n].x : (kk == 1) ? yv[n].y
                             : (kk == 2) ? yv[n].z : yv[n].w;
                    unsigned long long yd = dup2(y);
                    acc[n][0] = ffma2(yd, wlo, acc[n][0]);
                    acc[n][1] = ffma2(yd, whi, acc[n][1]);
                }
            }
        }

        // bias + relu per node, reduce over this warp's 8 nodes
        float b0 = bg[hb * 128 + lane * 4 + 0];
        float b1 = bg[hb * 128 + lane * 4 + 1];
        float b2 = bg[hb * 128 + lane * 4 + 2];
        float b3 = bg[hb * 128 + lane * 4 + 3];
        float h0 = 0.f, h1 = 0.f, h2 = 0.f, h3 = 0.f;
        #pragma unroll
        for (int n = 0; n < 8; n++) {
            float lo, hi;
            unpack2(acc[n][0], lo, hi);
            h0 += fmaxf(lo + b0, 0.0f);
            h1 += fmaxf(hi + b1, 0.0f);
            unpack2(acc[n][1], lo, hi);
            h2 += fmaxf(lo + b2, 0.0f);
            h3 += fmaxf(hi + b3, 0.0f);
        }
        atomicAdd(&gpart[lane * 4 + 0], h0);
        atomicAdd(&gpart[lane * 4 + 1], h1);
        atomicAdd(&gpart[lane * 4 + 2], h2);
        atomicAdd(&gpart[lane * 4 + 3], h3);
        __syncthreads();
        if (tid < 128) atomicAdd(&g_gacc[hb * 128 + tid], gpart[tid]);
    }
}

// ---------------------------------------------------------------------------
// K4: heads. out[0..63]=softmax(actor), out[64]=value
// ---------------------------------------------------------------------------
__global__ void k_head(const float* __restrict__ Wa1, const float* __restrict__ ba1,
                       const float* __restrict__ Wa2, const float* __restrict__ ba2,
                       const float* __restrict__ Wc1, const float* __restrict__ bc1,
                       const float* __restrict__ Wc2, const float* __restrict__ bc2,
                       float* __restrict__ out) {
    __shared__ float gg[H_DIM];
    __shared__ float hh[H_DIM];
    __shared__ float lg[A_DIM + 1];

    int t = threadIdx.x;             // 1024
    int lane = t & 31;
    int warp = t >> 5;               // 0..31

    if (t < H_DIM) gg[t] = g_gacc[t] * (1.0f / (float)N_NODES);
    __syncthreads();

    #pragma unroll
    for (int q = 0; q < 8; q++) {
        int o = warp * 8 + q;
        const float* Wrow = (o < 128) ? (Wa1 + (size_t)o * H_DIM)
                                      : (Wc1 + (size_t)(o - 128) * H_DIM);
        float bias = (o < 128) ? ba1[o] : bc1[o - 128];
        float s = 0.0f;
        #pragma unroll
        for (int j = 0; j < 8; j++)
            s += gg[lane + j * 32] * Wrow[lane + j * 32];
        #pragma unroll
        for (int off = 16; off > 0; off >>= 1)
            s += __shfl_down_sync(0xffffffffu, s, off);
        if (lane == 0) hh[o] = fmaxf(s + bias, 0.0f);
    }
    __syncthreads();

    #pragma unroll
    for (int q = 0; q < 2; q++) {
        int o = warp + q * 32;
        const float* Wrow = Wa2 + (size_t)o * (H_DIM / 2);
        float s = 0.0f;
        #pragma unroll
        for (int j = 0; j < 4; j++)
            s += hh[lane + j * 32] * Wrow[lane + j * 32];
        #pragma unroll
        for (int off = 16; off > 0; off >>= 1)
            s += __shfl_down_sync(0xffffffffu, s, off);
        if (lane == 0) lg[o] = s + ba2[o];
    }
    if (warp == 0) {
        float s = 0.0f;
        #pragma unroll
        for (int j = 0; j < 4; j++)
            s += hh[128 + lane + j * 32] * Wc2[lane + j * 32];
        #pragma unroll
        for (int off = 16; off > 0; off >>= 1)
            s += __shfl_down_sync(0xffffffffu, s, off);
        if (lane == 0) lg[A_DIM] = s + bc2[0];
    }
    __syncthreads();

    if (warp == 0) {
        float a = lg[lane], b = lg[lane + 32];
        float m = fmaxf(a, b);
        #pragma unroll
        for (int off = 16; off > 0; off >>= 1)
            m = fmaxf(m, __shfl_xor_sync(0xffffffffu, m, off));
        float ea = expf(a - m), eb = expf(b - m);
        float s = ea + eb;
        #pragma unroll
        for (int off = 16; off > 0; off >>= 1)
            s += __shfl_xor_sync(0xffffffffu, s, off);
        float inv = 1.0f / s;
        out[lane] = ea * inv;
        out[lane + 32] = eb * inv;
        if (lane == 0) out[A_DIM] = lg[A_DIM];
    }
}

// ---------------------------------------------------------------------------
extern "C" void kernel_launch(void* const* d_in, const int* in_sizes, int n_in,
                              void* d_out, int out_size) {
    const float* X   = (const float*)d_in[0];
    const int*   ei  = (const int*)  d_in[1];
    const float* Wg  = (const float*)d_in[2];
    const float* bg  = (const float*)d_in[3];
    const float* Wa1 = (const float*)d_in[4];
    const float* ba1 = (const float*)d_in[5];
    const float* Wa2 = (const float*)d_in[6];
    const float* ba2 = (const float*)d_in[7];
    const float* Wc1 = (const float*)d_in[8];
    const float* bc1 = (const float*)d_in[9];
    const float* Wc2 = (const float*)d_in[10];
    const float* bc2 = (const float*)d_in[11];
    float* out = (float*)d_out;

    cudaFuncSetAttribute(k_gemm, cudaFuncAttributeMaxDynamicSharedMemorySize,
                         GEMM_SMEM_BYTES);

    k_build<<<E_EDGES / 256, 256>>>(ei);
    k_gather<<<N_NODES / GW, GW * 32>>>(X);
    k_gemm<<<N_NODES / NB, 512, GEMM_SMEM_BYTES>>>(Wg, bg);
    k_head<<<1, 1024>>>(Wa1, ba1, Wa2, ba2, Wc1, bc1, Wc2, bc2, out);
}

// round 8
// speedup vs baseline: 1.4889x; 1.1400x over previous
#include <cuda_runtime.h>
#include <cuda_fp16.h>
#include <math.h>

#define N_NODES 16384
#define E_EDGES 524288
#define F_IN    128
#define H_DIM   256
#define A_DIM   64

#define CAP      128     // bucket capacity per source node (max raw degree ~57)
#define LIST_CAP 160
#define GW       16      // warps (nodes) per gather block
#define NB       128     // nodes per gemm block

// Scratch (static __device__ globals; zero-initialized at module load)
__device__ int    g_cnt[N_NODES];            // raw out-degree (re-zeroed by k_gather)
__device__ int    g_slot[N_NODES * CAP];     // bucketed dst lists (8 MB)
__device__ __half g_xh[N_NODES * F_IN];      // fp16 mirror of X (4 MB)
__device__ float  g_y[N_NODES * F_IN];       // normalized aggregated features (8 MB)
__device__ float  g_gacc[H_DIM];             // zeroed by k_build each run
__device__ float  g_hh[H_DIM];               // head layer-1 outputs

// ---------------------------------------------------------------------------
// Packed dual-FP32 helpers (Blackwell f32x2 -> SASS FFMA2). Bit-exact 2x fp32.
// ---------------------------------------------------------------------------
__device__ __forceinline__ unsigned long long ffma2(unsigned long long a,
                                                    unsigned long long b,
                                                    unsigned long long c) {
    unsigned long long d;
    asm("fma.rn.f32x2 %0, %1, %2, %3;" : "=l"(d) : "l"(a), "l"(b), "l"(c));
    return d;
}
__device__ __forceinline__ unsigned long long dup2(float x) {
    unsigned long long d;
    unsigned xb = __float_as_uint(x);
    asm("mov.b64 %0, {%1, %1};" : "=l"(d) : "r"(xb));
    return d;
}
__device__ __forceinline__ unsigned long long pack2(float lo, float hi) {
    unsigned long long d;
    asm("mov.b64 %0, {%1, %2};" : "=l"(d)
        : "r"(__float_as_uint(lo)), "r"(__float_as_uint(hi)));
    return d;
}
__device__ __forceinline__ void unpack2(unsigned long long v, float& lo, float& hi) {
    unsigned a, b;
    asm("mov.b64 {%0, %1}, %2;" : "=r"(a), "=r"(b) : "l"(v));
    lo = __uint_as_float(a);
    hi = __uint_as_float(b);
}
__device__ __forceinline__ void hacc(float4& acc, uint2 v) {
    __half2 h0 = *reinterpret_cast<__half2*>(&v.x);
    __half2 h1 = *reinterpret_cast<__half2*>(&v.y);
    float2 f0 = __half22float2(h0);
    float2 f1 = __half22float2(h1);
    acc.x += f0.x; acc.y += f0.y; acc.z += f1.x; acc.w += f1.y;
}

// ---------------------------------------------------------------------------
// K1: bucket build + fp16 mirror of X + g_gacc zero. One edge per thread;
// each thread also converts 4 X elements (E threads x 4 = N*F exactly).
// g_cnt is zero on entry (invariant restored by k_gather).
// ---------------------------------------------------------------------------
__global__ void k_build(const int* __restrict__ ei, const float* __restrict__ X) {
    int e = blockIdx.x * blockDim.x + threadIdx.x;
    if (e < H_DIM) g_gacc[e] = 0.0f;
    {
        float4 v = ((const float4*)X)[e];
        __half2 h0 = __floats2half2_rn(v.x, v.y);
        __half2 h1 = __floats2half2_rn(v.z, v.w);
        uint2 o;
        o.x = *reinterpret_cast<unsigned*>(&h0);
        o.y = *reinterpret_cast<unsigned*>(&h1);
        ((uint2*)g_xh)[e] = o;
    }
    int s = ei[e];
    int d = ei[E_EDGES + e];
    int pos = atomicAdd(&g_cnt[s], 1);
    if (pos < CAP) g_slot[s * CAP + pos] = d;
}

// ---------------------------------------------------------------------------
// K2: gather. One warp per node, 16 warps/block, 4 blocks/SM (64 warps/SM).
// Neighbor rows read fp16 (halves the L2-cap-bound traffic); identity row
// fp32 (exact). Dedup via per-warp smem bitmap.
// ---------------------------------------------------------------------------
__global__ __launch_bounds__(GW * 32, 4)
void k_gather(const float* __restrict__ X) {
    __shared__ unsigned bitmap_s[GW * 512];   // 32 KB
    __shared__ int      list_s[GW * LIST_CAP];// 10 KB

    int lane = threadIdx.x & 31;
    int warp = threadIdx.x >> 5;
    int n = blockIdx.x * GW + warp;

    unsigned* bitmap = bitmap_s + warp * 512;
    int*      list   = list_s + warp * LIST_CAP;
    const uint2* Xh2 = (const uint2*)g_xh;

    #pragma unroll
    for (int j = lane; j < 512; j += 32) bitmap[j] = 0u;
    __syncwarp();

    int len = g_cnt[n];
    if (len > CAP) len = CAP;
    const int* row = g_slot + n * CAP;
    int cnt = 0;
    for (int b = 0; b < len; b += 32) {
        int e = b + lane;
        int isnew = 0, d = 0;
        if (e < len) {
            d = row[e];
            unsigned m = 1u << (d & 31);
            unsigned old = atomicOr(&bitmap[d >> 5], m);
            isnew = ((old & m) == 0u);
        }
        unsigned bal = __ballot_sync(0xffffffffu, isnew);
        if (isnew) {
            int pos = cnt + __popc(bal & ((1u << lane) - 1u));
            if (pos < LIST_CAP) list[pos] = d;
        }
        cnt += __popc(bal);
    }
    if (cnt > LIST_CAP) cnt = LIST_CAP;
    __syncwarp();

    // acc = X[n] (exact fp32 identity) + sum_{unique d} Xh[d]
    float4 acc = ((const float4*)X)[(size_t)n * 32 + lane];
    int k = 0;
    for (; k + 8 <= cnt; k += 8) {
        uint2 v0 = Xh2[(size_t)list[k + 0] * 32 + lane];
        uint2 v1 = Xh2[(size_t)list[k + 1] * 32 + lane];
        uint2 v2 = Xh2[(size_t)list[k + 2] * 32 + lane];
        uint2 v3 = Xh2[(size_t)list[k + 3] * 32 + lane];
        uint2 v4 = Xh2[(size_t)list[k + 4] * 32 + lane];
        uint2 v5 = Xh2[(size_t)list[k + 5] * 32 + lane];
        uint2 v6 = Xh2[(size_t)list[k + 6] * 32 + lane];
        uint2 v7 = Xh2[(size_t)list[k + 7] * 32 + lane];
        hacc(acc, v0); hacc(acc, v1); hacc(acc, v2); hacc(acc, v3);
        hacc(acc, v4); hacc(acc, v5); hacc(acc, v6); hacc(acc, v7);
    }
    for (; k < cnt; k++)
        hacc(acc, Xh2[(size_t)list[k] * 32 + lane]);

    float inv = 1.0f / (float)(1 + cnt);
    acc.x *= inv; acc.y *= inv; acc.z *= inv; acc.w *= inv;
    ((float4*)(g_y + (size_t)n * F_IN))[lane] = acc;

    if (lane == 0) g_cnt[n] = 0;   // restore invariant for next replay
}

// ---------------------------------------------------------------------------
// K3: GEMM + relu + node-sum (round-7 conflict-free FFMA2 layout, unchanged).
// ---------------------------------------------------------------------------
#define GEMM_SMEM_FLOATS (NB * 128 + 128 * 128 + 128)
#define GEMM_SMEM_BYTES  (GEMM_SMEM_FLOATS * 4)

__global__ void k_gemm(const float* __restrict__ Wg, const float* __restrict__ bg) {
    extern __shared__ float smem[];
    float* ys    = smem;                 // [128 nodes][128 k]
    float* ws    = smem + NB * 128;      // [128 k][128 h]
    float* gpart = ws + 128 * 128;

    int tid  = threadIdx.x;              // 512
    int lane = tid & 31;
    int warp = tid >> 5;                 // 0..15
    int node0 = blockIdx.x * NB;

    const float4* Y4 = (const float4*)g_y;
    for (int idx = tid; idx < NB * 32; idx += 512) {
        int r  = idx >> 5;
        int k4 = idx & 31;
        ((float4*)(ys + r * 128))[k4] = Y4[(size_t)(node0 + r) * 32 + k4];
    }

    int nbase = warp * 8;

    for (int hb = 0; hb < 2; hb++) {
        __syncthreads();

        for (int idx = tid; idx < 128 * 32; idx += 512) {
            int h  = idx & 127;
            int k4 = idx >> 7;
            float4 w = ((const float4*)(Wg + (size_t)(hb * 128 + h) * F_IN))[k4];
            ws[(k4 * 4 + 0) * 128 + h] = w.x;
            ws[(k4 * 4 + 1) * 128 + h] = w.y;
            ws[(k4 * 4 + 2) * 128 + h] = w.z;
            ws[(k4 * 4 + 3) * 128 + h] = w.w;
        }
        if (tid < 128) gpart[tid] = 0.0f;
        __syncthreads();

        unsigned long long acc[8][2];
        #pragma unroll
        for (int n = 0; n < 8; n++) { acc[n][0] = 0ull; acc[n][1] = 0ull; }

        #pragma unroll 2
        for (int k4 = 0; k4 < 32; k4++) {
            float4 yv[8];
            #pragma unroll
            for (int n = 0; n < 8; n++)
                yv[n] = *((const float4*)(ys + (nbase + n) * 128 + k4 * 4));
            #pragma unroll
            for (int kk = 0; kk < 4; kk++) {
                int k = k4 * 4 + kk;
                float4 wv = *((const float4*)(ws + k * 128 + lane * 4));
                unsigned long long wlo = pack2(wv.x, wv.y);
                unsigned long long whi = pack2(wv.z, wv.w);
                #pragma unroll
                for (int n = 0; n < 8; n++) {
                    float y = (kk == 0) ? yv[n].x : (kk == 1) ? yv[n].y
                             : (kk == 2) ? yv[n].z : yv[n].w;
                    unsigned long long yd = dup2(y);
                    acc[n][0] = ffma2(yd, wlo, acc[n][0]);
                    acc[n][1] = ffma2(yd, whi, acc[n][1]);
                }
            }
        }

        float b0 = bg[hb * 128 + lane * 4 + 0];
        float b1 = bg[hb * 128 + lane * 4 + 1];
        float b2 = bg[hb * 128 + lane * 4 + 2];
        float b3 = bg[hb * 128 + lane * 4 + 3];
        float h0 = 0.f, h1 = 0.f, h2 = 0.f, h3 = 0.f;
        #pragma unroll
        for (int n = 0; n < 8; n++) {
            float lo, hi;
            unpack2(acc[n][0], lo, hi);
            h0 += fmaxf(lo + b0, 0.0f);
            h1 += fmaxf(hi + b1, 0.0f);
            unpack2(acc[n][1], lo, hi);
            h2 += fmaxf(lo + b2, 0.0f);
            h3 += fmaxf(hi + b3, 0.0f);
        }
        atomicAdd(&gpart[lane * 4 + 0], h0);
        atomicAdd(&gpart[lane * 4 + 1], h1);
        atomicAdd(&gpart[lane * 4 + 2], h2);
        atomicAdd(&gpart[lane * 4 + 3], h3);
        __syncthreads();
        if (tid < 128) atomicAdd(&g_gacc[hb * 128 + tid], gpart[tid]);
    }
}

// ---------------------------------------------------------------------------
// K4: head layer-1, parallelized across 32 blocks (warp-per-output).
// hh[o] = relu( (g_gacc . W[o]) / N + b[o] ),  o in [0,256)
// ---------------------------------------------------------------------------
__global__ void k_head1(const float* __restrict__ Wa1, const float* __restrict__ ba1,
                        const float* __restrict__ Wc1, const float* __restrict__ bc1) {
    int lane = threadIdx.x & 31;
    int warp = threadIdx.x >> 5;          // 0..7
    int o = blockIdx.x * 8 + warp;        // 0..255

    const float* Wrow = (o < 128) ? (Wa1 + (size_t)o * H_DIM)
                                  : (Wc1 + (size_t)(o - 128) * H_DIM);
    float bias = (o < 128) ? ba1[o] : bc1[o - 128];

    float s = 0.0f;
    #pragma unroll
    for (int j = 0; j < 8; j++) {
        int k = lane + j * 32;
        s += g_gacc[k] * Wrow[k];
    }
    #pragma unroll
    for (int off = 16; off > 0; off >>= 1)
        s += __shfl_down_sync(0xffffffffu, s, off);
    if (lane == 0)
        g_hh[o] = fmaxf(s * (1.0f / (float)N_NODES) + bias, 0.0f);
}

// ---------------------------------------------------------------------------
// K5: head layer-2 + softmax + value. One block, 1024 threads.
// out[0..63]=softmax(actor), out[64]=value
// ---------------------------------------------------------------------------
__global__ void k_head2(const float* __restrict__ Wa2, const float* __restrict__ ba2,
                        const float* __restrict__ Wc2, const float* __restrict__ bc2,
                        float* __restrict__ out) {
    __shared__ float hh[H_DIM];
    __shared__ float lg[A_DIM + 1];

    int t = threadIdx.x;             // 1024
    int lane = t & 31;
    int warp = t >> 5;               // 0..31

    if (t < H_DIM) hh[t] = g_hh[t];
    __syncthreads();

    #pragma unroll
    for (int q = 0; q < 2; q++) {
        int o = warp + q * 32;
        const float* Wrow = Wa2 + (size_t)o * (H_DIM / 2);
        float s = 0.0f;
        #pragma unroll
        for (int j = 0; j < 4; j++)
            s += hh[lane + j * 32] * Wrow[lane + j * 32];
        #pragma unroll
        for (int off = 16; off > 0; off >>= 1)
            s += __shfl_down_sync(0xffffffffu, s, off);
        if (lane == 0) lg[o] = s + ba2[o];
    }
    if (warp == 0) {
        float s = 0.0f;
        #pragma unroll
        for (int j = 0; j < 4; j++)
            s += hh[128 + lane + j * 32] * Wc2[lane + j * 32];
        #pragma unroll
        for (int off = 16; off > 0; off >>= 1)
            s += __shfl_down_sync(0xffffffffu, s, off);
        if (lane == 0) lg[A_DIM] = s + bc2[0];
    }
    __syncthreads();

    if (warp == 0) {
        float a = lg[lane], b = lg[lane + 32];
        float m = fmaxf(a, b);
        #pragma unroll
        for (int off = 16; off > 0; off >>= 1)
            m = fmaxf(m, __shfl_xor_sync(0xffffffffu, m, off));
        float ea = expf(a - m), eb = expf(b - m);
        float s = ea + eb;
        #pragma unroll
        for (int off = 16; off > 0; off >>= 1)
            s += __shfl_xor_sync(0xffffffffu, s, off);
        float inv = 1.0f / s;
        out[lane] = ea * inv;
        out[lane + 32] = eb * inv;
        if (lane == 0) out[A_DIM] = lg[A_DIM];
    }
}

// ---------------------------------------------------------------------------
extern "C" void kernel_launch(void* const* d_in, const int* in_sizes, int n_in,
                              void* d_out, int out_size) {
    const float* X   = (const float*)d_in[0];
    const int*   ei  = (const int*)  d_in[1];
    const float* Wg  = (const float*)d_in[2];
    const float* bg  = (const float*)d_in[3];
    const float* Wa1 = (const float*)d_in[4];
    const float* ba1 = (const float*)d_in[5];
    const float* Wa2 = (const float*)d_in[6];
    const float* ba2 = (const float*)d_in[7];
    const float* Wc1 = (const float*)d_in[8];
    const float* bc1 = (const float*)d_in[9];
    const float* Wc2 = (const float*)d_in[10];
    const float* bc2 = (const float*)d_in[11];
    float* out = (float*)d_out;

    cudaFuncSetAttribute(k_gemm, cudaFuncAttributeMaxDynamicSharedMemorySize,
                         GEMM_SMEM_BYTES);

    k_build<<<E_EDGES / 256, 256>>>(ei, X);
    k_gather<<<N_NODES / GW, GW * 32>>>(X);
    k_gemm<<<N_NODES / NB, 512, GEMM_SMEM_BYTES>>>(Wg, bg);
    k_head1<<<32, 256>>>(Wa1, ba1, Wc1, bc1);
    k_head2<<<1, 1024>>>(Wa2, ba2, Wc2, bc2, out);
}

// round 9
// speedup vs baseline: 1.9711x; 1.3239x over previous
#include <cuda_runtime.h>
#include <cuda_fp16.h>
#include <math.h>

#define N_NODES 16384
#define E_EDGES 524288
#define F_IN    128
#define H_DIM   256
#define A_DIM   64

#define CAP      128     // bucket capacity per source node (max raw degree ~57)
#define LIST_CAP 160
#define GW       16      // warps (nodes) per gather block
#define NB       128     // nodes per gemm block

// Scratch (static __device__ globals; zero-initialized at module load)
__device__ int    g_cnt[N_NODES];            // raw out-degree (re-zeroed by k_gather)
__device__ int    g_slot[N_NODES * CAP];     // bucketed dst lists (8 MB)
__device__ __half g_xh[N_NODES * F_IN];      // fp16 mirror of X (4 MB)
__device__ float  g_y[N_NODES * F_IN];       // normalized aggregated features (8 MB)
__device__ float  g_gacc[H_DIM];             // zeroed by k_build each run
__device__ float  g_hh[H_DIM];               // head layer-1 outputs

// ---------------------------------------------------------------------------
// helpers
// ---------------------------------------------------------------------------
__device__ __forceinline__ void hacc(float4& acc, uint2 v) {
    __half2 h0 = *reinterpret_cast<__half2*>(&v.x);
    __half2 h1 = *reinterpret_cast<__half2*>(&v.y);
    float2 f0 = __half22float2(h0);
    float2 f1 = __half22float2(h1);
    acc.x += f0.x; acc.y += f0.y; acc.z += f1.x; acc.w += f1.y;
}
__device__ __forceinline__ unsigned f2tf32(float f) {
    unsigned u;
    asm("cvt.rna.tf32.f32 %0, %1;" : "=r"(u) : "f"(f));
    return u;
}
__device__ __forceinline__ void mma_tf32(float d[4],
                                         unsigned a0, unsigned a1,
                                         unsigned a2, unsigned a3,
                                         unsigned b0, unsigned b1) {
    asm volatile(
        "mma.sync.aligned.m16n8k8.row.col.f32.tf32.tf32.f32 "
        "{%0,%1,%2,%3}, {%4,%5,%6,%7}, {%8,%9}, {%0,%1,%2,%3};"
        : "+f"(d[0]), "+f"(d[1]), "+f"(d[2]), "+f"(d[3])
        : "r"(a0), "r"(a1), "r"(a2), "r"(a3), "r"(b0), "r"(b1));
}

// ---------------------------------------------------------------------------
// K1: bucket build + fp16 mirror of X + g_gacc zero. One edge per thread.
// ---------------------------------------------------------------------------
__global__ void k_build(const int* __restrict__ ei, const float* __restrict__ X) {
    int e = blockIdx.x * blockDim.x + threadIdx.x;
    if (e < H_DIM) g_gacc[e] = 0.0f;
    {
        float4 v = ((const float4*)X)[e];
        __half2 h0 = __floats2half2_rn(v.x, v.y);
        __half2 h1 = __floats2half2_rn(v.z, v.w);
        uint2 o;
        o.x = *reinterpret_cast<unsigned*>(&h0);
        o.y = *reinterpret_cast<unsigned*>(&h1);
        ((uint2*)g_xh)[e] = o;
    }
    int s = ei[e];
    int d = ei[E_EDGES + e];
    int pos = atomicAdd(&g_cnt[s], 1);
    if (pos < CAP) g_slot[s * CAP + pos] = d;
}

// ---------------------------------------------------------------------------
// K2: gather. One warp per node, fp16 neighbor reads, fp32 identity + accum.
// ---------------------------------------------------------------------------
__global__ __launch_bounds__(GW * 32, 4)
void k_gather(const float* __restrict__ X) {
    __shared__ unsigned bitmap_s[GW * 512];
    __shared__ int      list_s[GW * LIST_CAP];

    int lane = threadIdx.x & 31;
    int warp = threadIdx.x >> 5;
    int n = blockIdx.x * GW + warp;

    unsigned* bitmap = bitmap_s + warp * 512;
    int*      list   = list_s + warp * LIST_CAP;
    const uint2* Xh2 = (const uint2*)g_xh;

    #pragma unroll
    for (int j = lane; j < 512; j += 32) bitmap[j] = 0u;
    __syncwarp();

    int len = g_cnt[n];
    if (len > CAP) len = CAP;
    const int* row = g_slot + n * CAP;
    int cnt = 0;
    for (int b = 0; b < len; b += 32) {
        int e = b + lane;
        int isnew = 0, d = 0;
        if (e < len) {
            d = row[e];
            unsigned m = 1u << (d & 31);
            unsigned old = atomicOr(&bitmap[d >> 5], m);
            isnew = ((old & m) == 0u);
        }
        unsigned bal = __ballot_sync(0xffffffffu, isnew);
        if (isnew) {
            int pos = cnt + __popc(bal & ((1u << lane) - 1u));
            if (pos < LIST_CAP) list[pos] = d;
        }
        cnt += __popc(bal);
    }
    if (cnt > LIST_CAP) cnt = LIST_CAP;
    __syncwarp();

    float4 acc = ((const float4*)X)[(size_t)n * 32 + lane];
    int k = 0;
    for (; k + 8 <= cnt; k += 8) {
        uint2 v0 = Xh2[(size_t)list[k + 0] * 32 + lane];
        uint2 v1 = Xh2[(size_t)list[k + 1] * 32 + lane];
        uint2 v2 = Xh2[(size_t)list[k + 2] * 32 + lane];
        uint2 v3 = Xh2[(size_t)list[k + 3] * 32 + lane];
        uint2 v4 = Xh2[(size_t)list[k + 4] * 32 + lane];
        uint2 v5 = Xh2[(size_t)list[k + 5] * 32 + lane];
        uint2 v6 = Xh2[(size_t)list[k + 6] * 32 + lane];
        uint2 v7 = Xh2[(size_t)list[k + 7] * 32 + lane];
        hacc(acc, v0); hacc(acc, v1); hacc(acc, v2); hacc(acc, v3);
        hacc(acc, v4); hacc(acc, v5); hacc(acc, v6); hacc(acc, v7);
    }
    for (; k < cnt; k++)
        hacc(acc, Xh2[(size_t)list[k] * 32 + lane]);

    float inv = 1.0f / (float)(1 + cnt);
    acc.x *= inv; acc.y *= inv; acc.z *= inv; acc.w *= inv;
    ((float4*)(g_y + (size_t)n * F_IN))[lane] = acc;

    if (lane == 0) g_cnt[n] = 0;
}

// ---------------------------------------------------------------------------
// K3: tensor-core GEMM (mma.sync m16n8k8 tf32) + relu + node-sum.
// 512 threads = 16 warps; block: 128 nodes x 256 h in ONE pass.
// Warp w: m32 tile mt=w&3 (nodes mt*32..+32), n64 tile nt=w>>2 (h nt*64..+64).
// Padded strides: ys 132 (A frags conflict-free), ws 264 (B frags conflict-free).
// smem: ys 128*132 + ws 128*264 + gpart 256 = 203,776 B
// ---------------------------------------------------------------------------
#define YS_STRIDE 132
#define WS_STRIDE 264
#define GEMM_SMEM_BYTES ((NB * YS_STRIDE + 128 * WS_STRIDE + 256) * 4)

__global__ void k_gemm(const float* __restrict__ Wg, const float* __restrict__ bg) {
    extern __shared__ float smem[];
    float* ys    = smem;                          // [128 nodes][132]
    float* ws    = smem + NB * YS_STRIDE;         // [128 k][264] (256 h used)
    float* gpart = ws + 128 * WS_STRIDE;          // [256]

    unsigned* ysu = (unsigned*)ys;
    unsigned* wsu = (unsigned*)ws;

    int tid  = threadIdx.x;              // 512
    int lane = tid & 31;
    int warp = tid >> 5;                 // 0..15
    int node0 = blockIdx.x * NB;

    int g  = lane >> 2;                  // 0..7
    int t4 = lane & 3;                   // 0..3
    int mt = warp & 3;                   // m32 tile
    int nt = warp >> 2;                  // n64 tile
    int ntb = nt * 64;                   // h base

    if (tid < 256) gpart[tid] = 0.0f;

    // Fill ys: Y (fp32) -> tf32 bits. Coalesced LDG.128.
    const float4* Y4 = (const float4*)g_y;
    for (int idx = tid; idx < NB * 32; idx += 512) {
        int r  = idx >> 5;
        int k4 = idx & 31;
        float4 v = Y4[(size_t)(node0 + r) * 32 + k4];
        uint4 o = make_uint4(f2tf32(v.x), f2tf32(v.y), f2tf32(v.z), f2tf32(v.w));
        *((uint4*)(ysu + r * YS_STRIDE + k4 * 4)) = o;
    }
    // Fill ws: W[h][k] -> ws[k][h] tf32 bits (consecutive tid -> consecutive h)
    for (int idx = tid; idx < 256 * 32; idx += 512) {
        int h  = idx & 255;
        int k4 = idx >> 8;
        float4 w = ((const float4*)(Wg + (size_t)h * F_IN))[k4];
        wsu[(k4 * 4 + 0) * WS_STRIDE + h] = f2tf32(w.x);
        wsu[(k4 * 4 + 1) * WS_STRIDE + h] = f2tf32(w.y);
        wsu[(k4 * 4 + 2) * WS_STRIDE + h] = f2tf32(w.z);
        wsu[(k4 * 4 + 3) * WS_STRIDE + h] = f2tf32(w.w);
    }
    __syncthreads();

    // Accumulators: 2 m16-subtiles x 8 n8-subtiles x 4 regs
    float d[2][8][4];
    #pragma unroll
    for (int mi = 0; mi < 2; mi++)
        #pragma unroll
        for (int j = 0; j < 8; j++)
            #pragma unroll
            for (int q = 0; q < 4; q++) d[mi][j][q] = 0.0f;

    #pragma unroll 4
    for (int ks = 0; ks < 16; ks++) {
        int k0 = ks * 8;
        unsigned a[2][4];
        #pragma unroll
        for (int mi = 0; mi < 2; mi++) {
            int row = mt * 32 + mi * 16 + g;
            // A frag (m16n8k8 row-major): a0(g,t4) a1(g+8,t4) a2(g,t4+4) a3(g+8,t4+4)
            a[mi][0] = ysu[(row)     * YS_STRIDE + k0 + t4];
            a[mi][1] = ysu[(row + 8) * YS_STRIDE + k0 + t4];
            a[mi][2] = ysu[(row)     * YS_STRIDE + k0 + t4 + 4];
            a[mi][3] = ysu[(row + 8) * YS_STRIDE + k0 + t4 + 4];
        }
        #pragma unroll
        for (int j = 0; j < 8; j++) {
            // B frag (k8 x n8 col-major): b0(k=t4, n=g) b1(k=t4+4, n=g)
            unsigned b0 = wsu[(k0 + t4)     * WS_STRIDE + ntb + j * 8 + g];
            unsigned b1 = wsu[(k0 + t4 + 4) * WS_STRIDE + ntb + j * 8 + g];
            mma_tf32(d[0][j], a[0][0], a[0][1], a[0][2], a[0][3], b0, b1);
            mma_tf32(d[1][j], a[1][0], a[1][1], a[1][2], a[1][3], b0, b1);
        }
    }

    // Epilogue: bias + relu per node (in-register), sum nodes, reduce over g.
    #pragma unroll
    for (int j = 0; j < 8; j++) {
        int h0 = ntb + j * 8 + 2 * t4;
        float bias0 = bg[h0];
        float bias1 = bg[h0 + 1];
        // D frag: c0(g,2t4) c1(g,2t4+1) c2(g+8,2t4) c3(g+8,2t4+1)
        float s0 = 0.0f, s1 = 0.0f;
        #pragma unroll
        for (int mi = 0; mi < 2; mi++) {
            s0 += fmaxf(d[mi][j][0] + bias0, 0.0f) + fmaxf(d[mi][j][2] + bias0, 0.0f);
            s1 += fmaxf(d[mi][j][1] + bias1, 0.0f) + fmaxf(d[mi][j][3] + bias1, 0.0f);
        }
        // reduce over g (lanes t4, t4+4, ..., t4+28)
        #pragma unroll
        for (int off = 16; off >= 4; off >>= 1) {
            s0 += __shfl_down_sync(0xffffffffu, s0, off);
            s1 += __shfl_down_sync(0xffffffffu, s1, off);
        }
        if (lane < 4) {
            atomicAdd(&gpart[ntb + j * 8 + 2 * lane],     s0);
            atomicAdd(&gpart[ntb + j * 8 + 2 * lane + 1], s1);
        }
    }
    __syncthreads();
    if (tid < 256) atomicAdd(&g_gacc[tid], gpart[tid]);
}

// ---------------------------------------------------------------------------
// K4: head layer-1 across 32 blocks (warp-per-output).
// ---------------------------------------------------------------------------
__global__ void k_head1(const float* __restrict__ Wa1, const float* __restrict__ ba1,
                        const float* __restrict__ Wc1, const float* __restrict__ bc1) {
    int lane = threadIdx.x & 31;
    int warp = threadIdx.x >> 5;
    int o = blockIdx.x * 8 + warp;

    const float* Wrow = (o < 128) ? (Wa1 + (size_t)o * H_DIM)
                                  : (Wc1 + (size_t)(o - 128) * H_DIM);
    float bias = (o < 128) ? ba1[o] : bc1[o - 128];

    float s = 0.0f;
    #pragma unroll
    for (int j = 0; j < 8; j++) {
        int k = lane + j * 32;
        s += g_gacc[k] * Wrow[k];
    }
    #pragma unroll
    for (int off = 16; off > 0; off >>= 1)
        s += __shfl_down_sync(0xffffffffu, s, off);
    if (lane == 0)
        g_hh[o] = fmaxf(s * (1.0f / (float)N_NODES) + bias, 0.0f);
}

// ---------------------------------------------------------------------------
// K5: head layer-2 + softmax + value. One block.
// ---------------------------------------------------------------------------
__global__ void k_head2(const float* __restrict__ Wa2, const float* __restrict__ ba2,
                        const float* __restrict__ Wc2, const float* __restrict__ bc2,
                        float* __restrict__ out) {
    __shared__ float hh[H_DIM];
    __shared__ float lg[A_DIM + 1];

    int t = threadIdx.x;             // 1024
    int lane = t & 31;
    int warp = t >> 5;

    if (t < H_DIM) hh[t] = g_hh[t];
    __syncthreads();

    #pragma unroll
    for (int q = 0; q < 2; q++) {
        int o = warp + q * 32;
        const float* Wrow = Wa2 + (size_t)o * (H_DIM / 2);
        float s = 0.0f;
        #pragma unroll
        for (int j = 0; j < 4; j++)
            s += hh[lane + j * 32] * Wrow[lane + j * 32];
        #pragma unroll
        for (int off = 16; off > 0; off >>= 1)
            s += __shfl_down_sync(0xffffffffu, s, off);
        if (lane == 0) lg[o] = s + ba2[o];
    }
    if (warp == 0) {
        float s = 0.0f;
        #pragma unroll
        for (int j = 0; j < 4; j++)
            s += hh[128 + lane + j * 32] * Wc2[lane + j * 32];
        #pragma unroll
        for (int off = 16; off > 0; off >>= 1)
            s += __shfl_down_sync(0xffffffffu, s, off);
        if (lane == 0) lg[A_DIM] = s + bc2[0];
    }
    __syncthreads();

    if (warp == 0) {
        float a = lg[lane], b = lg[lane + 32];
        float m = fmaxf(a, b);
        #pragma unroll
        for (int off = 16; off > 0; off >>= 1)
            m = fmaxf(m, __shfl_xor_sync(0xffffffffu, m, off));
        float ea = expf(a - m), eb = expf(b - m);
        float s = ea + eb;
        #pragma unroll
        for (int off = 16; off > 0; off >>= 1)
            s += __shfl_xor_sync(0xffffffffu, s, off);
        float inv = 1.0f / s;
        out[lane] = ea * inv;
        out[lane + 32] = eb * inv;
        if (lane == 0) out[A_DIM] = lg[A_DIM];
    }
}

// ---------------------------------------------------------------------------
extern "C" void kernel_launch(void* const* d_in, const int* in_sizes, int n_in,
                              void* d_out, int out_size) {
    const float* X   = (const float*)d_in[0];
    const int*   ei  = (const int*)  d_in[1];
    const float* Wg  = (const float*)d_in[2];
    const float* bg  = (const float*)d_in[3];
    const float* Wa1 = (const float*)d_in[4];
    const float* ba1 = (const float*)d_in[5];
    const float* Wa2 = (const float*)d_in[6];
    const float* ba2 = (const float*)d_in[7];
    const float* Wc1 = (const float*)d_in[8];
    const float* bc1 = (const float*)d_in[9];
    const float* Wc2 = (const float*)d_in[10];
    const float* bc2 = (const float*)d_in[11];
    float* out = (float*)d_out;

    cudaFuncSetAttribute(k_gemm, cudaFuncAttributeMaxDynamicSharedMemorySize,
                         GEMM_SMEM_BYTES);

    k_build<<<E_EDGES / 256, 256>>>(ei, X);
    k_gather<<<N_NODES / GW, GW * 32>>>(X);
    k_gemm<<<N_NODES / NB, 512, GEMM_SMEM_BYTES>>>(Wg, bg);
    k_head1<<<32, 256>>>(Wa1, ba1, Wc1, bc1);
    k_head2<<<1, 1024>>>(Wa2, ba2, Wc2, bc2, out);
}